// round 5
// baseline (speedup 1.0000x reference)
#include <cuda_runtime.h>
#include <math.h>
#include <stdint.h>

#define B_   32
#define S_   2048
#define D_   400
#define H_   512
#define KP_D 416               // 400 padded to /32
#define MS   (B_*S_)

// ---------------- fp32 intermediates ----------------
__device__ float g_q   [(long)MS*H_];
__device__ float g_k   [(long)MS*H_];
__device__ float g_vT  [(long)B_*H_*S_];
__device__ float g_sc  [(long)B_*S_*S_];     // scores fp32
__device__ float g_out [(long)MS*H_];
__device__ float g_proj[(long)MS*D_];

// ---------------- int8 planes + row scales ----------------
__device__ int8_t g_rgb1 [(long)MS*KP_D], g_rgb2 [(long)MS*KP_D];
__device__ int8_t g_pose1[(long)MS*KP_D], g_pose2[(long)MS*KP_D];
__device__ float  g_srgb[MS], g_spose[MS];
__device__ int8_t g_wq1[H_*KP_D], g_wq2[H_*KP_D];
__device__ int8_t g_wk1[H_*KP_D], g_wk2[H_*KP_D];
__device__ int8_t g_wv1[H_*KP_D], g_wv2[H_*KP_D];
__device__ int8_t g_wp1[D_*H_],   g_wp2[D_*H_];
__device__ float  g_swq[H_], g_swk[H_], g_swv[H_], g_swp[D_];
__device__ int8_t g_q1[(long)MS*H_], g_q2[(long)MS*H_];
__device__ int8_t g_k1[(long)MS*H_], g_k2[(long)MS*H_];
__device__ float  g_sq[MS], g_sk[MS];
__device__ int8_t g_v1[(long)B_*H_*S_], g_v2[(long)B_*H_*S_];
__device__ float  g_sv[B_*H_];
__device__ int8_t g_a1[(long)B_*S_*S_], g_a2[(long)B_*S_*S_];
__device__ float  g_sat[MS];
__device__ int8_t g_o1[(long)MS*H_], g_o2[(long)MS*H_];
__device__ float  g_so[MS];

// ---------------------------------------------------------------------------
// Generic row quantizer: per-row scale s = maxabs/127, two s8 slices:
// x ~= s*(x1 + x2/128). Warp per row. K%4==0, Kp%32==0, pad zero-filled.
// ---------------------------------------------------------------------------
__global__ void quant_rows(const float* __restrict__ in, long R, int K, int Kp,
                           int8_t* __restrict__ p1, int8_t* __restrict__ p2,
                           float* __restrict__ sc) {
    long row = (long)blockIdx.x * 8 + (threadIdx.x >> 5);
    if (row >= R) return;
    const int lane = threadIdx.x & 31;
    const float* x = in + row * (long)K;

    float m = 0.f;
    for (int c = lane * 4; c < K; c += 128) {
        float4 v = *(const float4*)(x + c);
        m = fmaxf(m, fmaxf(fmaxf(fabsf(v.x), fabsf(v.y)),
                           fmaxf(fabsf(v.z), fabsf(v.w))));
    }
#pragma unroll
    for (int o = 16; o > 0; o >>= 1) m = fmaxf(m, __shfl_xor_sync(~0u, m, o));

    const float s = fmaxf(m, 1e-20f) * (1.f / 127.f);
    const float i1 = 1.f / s, i2 = 128.f / s;
    if (lane == 0) sc[row] = s;

    for (int c = lane * 4; c < Kp; c += 128) {
        float4 v = (c < K) ? *(const float4*)(x + c)
                           : make_float4(0.f, 0.f, 0.f, 0.f);
        int h0 = __float2int_rn(v.x * i1); int l0 = __float2int_rn((v.x - h0 * s) * i2);
        int h1 = __float2int_rn(v.y * i1); int l1 = __float2int_rn((v.y - h1 * s) * i2);
        int h2 = __float2int_rn(v.z * i1); int l2 = __float2int_rn((v.z - h2 * s) * i2);
        int h3 = __float2int_rn(v.w * i1); int l3 = __float2int_rn((v.w - h3 * s) * i2);
        *(char4*)(p1 + row * (long)Kp + c) = make_char4((char)h0,(char)h1,(char)h2,(char)h3);
        *(char4*)(p2 + row * (long)Kp + c) = make_char4((char)l0,(char)l1,(char)l2,(char)l3);
    }
}

// ---------------------------------------------------------------------------
// Fused weight prep: transpose + quantize all 4 weights. Warp per output row.
// rows [0,1536): WqT/WkT/WvT rows (h over d, K=400,Kp=416)
// rows [1536,1936): WpT rows (d over h, K=512)
// ---------------------------------------------------------------------------
__global__ void prep_weights(const float* __restrict__ Wq, const float* __restrict__ Wk,
                             const float* __restrict__ Wv, const float* __restrict__ Wp) {
    int r = blockIdx.x * 8 + (threadIdx.x >> 5);
    if (r >= 1936) return;
    const int lane = threadIdx.x & 31;

    const float* src; int K, Kp, stride;
    int8_t *p1, *p2; float* sc; int orow;
    if (r < 1536) {
        int role = r >> 9, h = r & 511;
        src = (role == 0 ? Wq : role == 1 ? Wk : Wv) + h;  // col h, stride H_
        K = D_; Kp = KP_D; stride = H_;
        p1 = (role == 0 ? g_wq1 : role == 1 ? g_wk1 : g_wv1);
        p2 = (role == 0 ? g_wq2 : role == 1 ? g_wk2 : g_wv2);
        sc = (role == 0 ? g_swq : role == 1 ? g_swk : g_swv);
        orow = h;
    } else {
        int d = r - 1536;
        src = Wp + d; K = H_; Kp = H_; stride = D_;
        p1 = g_wp1; p2 = g_wp2; sc = g_swp; orow = d;
    }

    float m = 0.f;
    for (int c = lane; c < K; c += 32) m = fmaxf(m, fabsf(src[(long)c * stride]));
#pragma unroll
    for (int o = 16; o > 0; o >>= 1) m = fmaxf(m, __shfl_xor_sync(~0u, m, o));
    const float s = fmaxf(m, 1e-20f) * (1.f / 127.f);
    const float i1 = 1.f / s, i2 = 128.f / s;
    if (lane == 0) sc[orow] = s;

    for (int c = lane; c < Kp; c += 32) {
        float x = (c < K) ? src[(long)c * stride] : 0.f;
        int h = __float2int_rn(x * i1);
        int l = __float2int_rn((x - h * s) * i2);
        p1[(long)orow * Kp + c] = (char)h;
        p2[(long)orow * Kp + c] = (char)l;
    }
}

// ---------------------------------------------------------------------------
// int8 2-slice NT GEMM:
// C[m][n] = alpha*sa[m]*sb[n]*(d1 + d2/128) (+bias_n)(+bias_m)
// where d1 = A1.B1, d2 = A1.B2 + A2.B1 (int32 exact).
// CTA 128x128, 8 warps of 64x32, K_TILE=32, cp.async double buffer.
// M%128==0; N tail guarded; Kp%32==0 (planes pre-padded).
// ---------------------------------------------------------------------------
#define PITCH 80      // bytes per smem row: 32(s1)+32(s2)+16 pad; conflict-free
#define STG   (128 * PITCH)

__device__ __forceinline__ void imma(int* d, const uint32_t* a, const uint32_t* b) {
    asm volatile(
        "mma.sync.aligned.m16n8k32.row.col.s32.s8.s8.s32 "
        "{%0,%1,%2,%3}, {%4,%5,%6,%7}, {%8,%9}, {%0,%1,%2,%3};\n"
        : "+r"(d[0]), "+r"(d[1]), "+r"(d[2]), "+r"(d[3])
        : "r"(a[0]), "r"(a[1]), "r"(a[2]), "r"(a[3]), "r"(b[0]), "r"(b[1]));
}

__global__ void __launch_bounds__(256, 1)
gemm_i8(const int8_t* __restrict__ A1, const int8_t* __restrict__ A2,
        const float* __restrict__ sa, long bsA, long bsSA,
        const int8_t* __restrict__ B1, const int8_t* __restrict__ B2,
        const float* __restrict__ sb, long bsB, long bsSB,
        float* __restrict__ C, long bsC,
        int M, int N, int Kp, float alpha,
        const float* __restrict__ bias_n, const float* __restrict__ bias_m) {
    __shared__ char sm[4 * STG];   // A0 B0 A1 B1

    const int tid = threadIdx.x;
    const int lane = tid & 31, wid = tid >> 5;
    const int wr = wid & 1, wc = wid >> 1;
    const int g = lane >> 2, tg = lane & 3;

    const long z = blockIdx.z;
    A1 += z * bsA; A2 += z * bsA; sa += z * bsSA;
    B1 += z * bsB; B2 += z * bsB; sb += z * bsSB;
    C  += z * bsC;
    const int m0 = blockIdx.y * 128;
    const int n0 = blockIdx.x * 128;

    // cp.async mapping: 1024 16B chunks (A 512 + B 512), 4 per thread
    const int8_t* gsrc[4]; unsigned sdst[4], ssz[4];
    {
        const unsigned base = (unsigned)__cvta_generic_to_shared(sm);
#pragma unroll
        for (int i = 0; i < 4; i++) {
            int c = tid + i * 256;            // 0..1023
            int isB = c >> 9;                  // 0:A 1:B
            int cc = c & 511;
            int row = cc >> 2, piece = cc & 3;
            int slice = piece >> 1, half = piece & 1;
            sdst[i] = base + isB * STG + row * PITCH + slice * 32 + half * 16;
            if (!isB) {
                gsrc[i] = (slice ? A2 : A1) + (long)(m0 + row) * Kp + half * 16;
                ssz[i] = 16u;
            } else {
                int gn = n0 + row;
                int ok = gn < N;
                gsrc[i] = (slice ? B2 : B1) + (long)(ok ? gn : 0) * Kp + half * 16;
                ssz[i] = ok ? 16u : 0u;
            }
        }
    }

#define LOADST(bufofs, kb) do {                                               \
    _Pragma("unroll")                                                         \
    for (int i = 0; i < 4; i++)                                               \
        asm volatile("cp.async.cg.shared.global [%0], [%1], 16, %2;\n"        \
                     :: "r"(sdst[i] + (bufofs)), "l"(gsrc[i] + (kb)), "r"(ssz[i])); \
    asm volatile("cp.async.commit_group;\n");                                 \
} while (0)

    int d1[4][4][4], d2[4][4][4];
#pragma unroll
    for (int i = 0; i < 4; i++)
#pragma unroll
        for (int j = 0; j < 4; j++)
#pragma unroll
            for (int c = 0; c < 4; c++) { d1[i][j][c] = 0; d2[i][j][c] = 0; }

    const int T = Kp / 32;
    LOADST(0, 0);

    for (int t = 0; t < T; t++) {
        const int buf = t & 1;
        if (t + 1 < T) {
            LOADST((buf ^ 1) * 2 * STG, (long)(t + 1) * 32);
            asm volatile("cp.async.wait_group 1;\n");
        } else {
            asm volatile("cp.async.wait_group 0;\n");
        }
        __syncthreads();

        const char* Ab = sm + buf * 2 * STG;
        const char* Bb = Ab + STG;

        uint32_t a1f[4][4], a2f[4][4], b1f[4][2], b2f[4][2];
#pragma unroll
        for (int i = 0; i < 4; i++) {
            const uint32_t* p = (const uint32_t*)(Ab + (wr * 64 + i * 16 + g) * PITCH + 4 * tg);
            a1f[i][0] = p[0];   a1f[i][1] = p[160];  // +8 rows = 8*20 words
            a1f[i][2] = p[4];   a1f[i][3] = p[164];
            a2f[i][0] = p[8];   a2f[i][1] = p[168];
            a2f[i][2] = p[12];  a2f[i][3] = p[172];
        }
#pragma unroll
        for (int j = 0; j < 4; j++) {
            const uint32_t* p = (const uint32_t*)(Bb + (wc * 32 + j * 8 + g) * PITCH + 4 * tg);
            b1f[j][0] = p[0]; b1f[j][1] = p[4];
            b2f[j][0] = p[8]; b2f[j][1] = p[12];
        }
#pragma unroll
        for (int i = 0; i < 4; i++)
#pragma unroll
            for (int j = 0; j < 4; j++) {
                imma(d1[i][j], a1f[i], b1f[j]);
                imma(d2[i][j], a1f[i], b2f[j]);
                imma(d2[i][j], a2f[i], b1f[j]);
            }
        __syncthreads();
    }

    // epilogue
#pragma unroll
    for (int i = 0; i < 4; i++) {
        const int r0 = m0 + wr * 64 + i * 16 + g;
        const int r1 = r0 + 8;
        const float f0 = alpha * sa[r0], f1 = alpha * sa[r1];
        const float bm0 = bias_m ? bias_m[r0] : 0.f;
        const float bm1 = bias_m ? bias_m[r1] : 0.f;
#pragma unroll
        for (int j = 0; j < 4; j++) {
            const int c0 = n0 + wc * 32 + j * 8 + 2 * tg;
            if (c0 < N) {
                const float sb0 = sb[c0], sb1 = sb[c0 + 1];
                const float bn0 = bias_n ? bias_n[c0]     : 0.f;
                const float bn1 = bias_n ? bias_n[c0 + 1] : 0.f;
                float v00 = f0 * sb0 * ((float)d1[i][j][0] + (float)d2[i][j][0] * 0.0078125f) + bm0 + bn0;
                float v01 = f0 * sb1 * ((float)d1[i][j][1] + (float)d2[i][j][1] * 0.0078125f) + bm0 + bn1;
                float v10 = f1 * sb0 * ((float)d1[i][j][2] + (float)d2[i][j][2] * 0.0078125f) + bm1 + bn0;
                float v11 = f1 * sb1 * ((float)d1[i][j][3] + (float)d2[i][j][3] * 0.0078125f) + bm1 + bn1;
                *(float2*)&C[(long)r0 * N + c0] = make_float2(v00, v01);
                *(float2*)&C[(long)r1 * N + c0] = make_float2(v10, v11);
            }
        }
    }
}

// ---------------------------------------------------------------------------
// Softmax over 2048 cols, emits int8 slices + row scale directly.
// ---------------------------------------------------------------------------
__global__ void __launch_bounds__(256)
softmax_q(const float* __restrict__ scores, int8_t* __restrict__ a1,
          int8_t* __restrict__ a2, float* __restrict__ sat) {
    const long rowi = blockIdx.x;
    const float* row = scores + rowi * 2048;
    const int tid = threadIdx.x;
    __shared__ float red[8];

    float v[8];
    float m = -3.4e38f;
#pragma unroll
    for (int i = 0; i < 8; i++) { v[i] = row[tid + i * 256]; m = fmaxf(m, v[i]); }
#pragma unroll
    for (int o = 16; o > 0; o >>= 1) m = fmaxf(m, __shfl_xor_sync(~0u, m, o));
    if ((tid & 31) == 0) red[tid >> 5] = m;
    __syncthreads();
    float rowmax = red[0];
#pragma unroll
    for (int w = 1; w < 8; w++) rowmax = fmaxf(rowmax, red[w]);
    __syncthreads();

    float s = 0.f;
#pragma unroll
    for (int i = 0; i < 8; i++) { v[i] = __expf(v[i] - rowmax); s += v[i]; }
#pragma unroll
    for (int o = 16; o > 0; o >>= 1) s += __shfl_xor_sync(~0u, s, o);
    if ((tid & 31) == 0) red[tid >> 5] = s;
    __syncthreads();
    float tot = 0.f;
#pragma unroll
    for (int w = 0; w < 8; w++) tot += red[w];
    const float inv = 1.f / tot;

    const float scl = inv * (1.f / 127.f);   // row scale (max prob = inv)
    const float i2 = 128.f / scl;
    if (tid == 0) sat[rowi] = scl;
#pragma unroll
    for (int i = 0; i < 8; i++) {
        float p = v[i] * inv;
        int h = __float2int_rn(127.f * v[i]);
        int l = __float2int_rn((p - h * scl) * i2);
        a1[rowi * 2048 + tid + i * 256] = (char)h;
        a2[rowi * 2048 + tid + i * 256] = (char)l;
    }
}

// ---------------------------------------------------------------------------
__global__ void __launch_bounds__(128)
ln_epilogue(const float* __restrict__ proj, const float* __restrict__ rgb,
            const float* __restrict__ gate, const float* __restrict__ gamma,
            const float* __restrict__ beta, float* __restrict__ out) {
    const long row = blockIdx.x;
    const int tid = threadIdx.x;
    const float g = gate[0];
    __shared__ float xs[D_];
    __shared__ float red[4];

    float s = 0.f;
    for (int i = tid; i < D_; i += 128) {
        float x = rgb[row * D_ + i] + g * proj[row * D_ + i];
        xs[i] = x;
        s += x;
    }
#pragma unroll
    for (int o = 16; o > 0; o >>= 1) s += __shfl_xor_sync(~0u, s, o);
    if ((tid & 31) == 0) red[tid >> 5] = s;
    __syncthreads();
    float mu = (red[0] + red[1] + red[2] + red[3]) * (1.0f / D_);
    __syncthreads();

    float vs = 0.f;
    for (int i = tid; i < D_; i += 128) {
        float d = xs[i] - mu;
        vs += d * d;
    }
#pragma unroll
    for (int o = 16; o > 0; o >>= 1) vs += __shfl_xor_sync(~0u, vs, o);
    if ((tid & 31) == 0) red[tid >> 5] = vs;
    __syncthreads();
    float var = (red[0] + red[1] + red[2] + red[3]) * (1.0f / D_);
    float inv = rsqrtf(var + 1e-5f);

    for (int i = tid; i < D_; i += 128) {
        out[row * D_ + i] = (xs[i] - mu) * inv * gamma[i] + beta[i];
    }
}

// ---------------------------------------------------------------------------
template <typename T>
static T* sym(const void* s) {
    void* p = nullptr;
    cudaGetSymbolAddress(&p, s);
    return (T*)p;
}

extern "C" void kernel_launch(void* const* d_in, const int* in_sizes, int n_in,
                              void* d_out, int out_size) {
    const float* rgb   = (const float*)d_in[0];
    const float* pose  = (const float*)d_in[1];
    const float* Wq    = (const float*)d_in[2];
    const float* bq    = (const float*)d_in[3];
    const float* Wk    = (const float*)d_in[4];
    const float* bk    = (const float*)d_in[5];
    const float* Wv    = (const float*)d_in[6];
    const float* bv    = (const float*)d_in[7];
    const float* Wp    = (const float*)d_in[8];
    const float* bp    = (const float*)d_in[9];
    const float* gamma = (const float*)d_in[10];
    const float* beta  = (const float*)d_in[11];
    const float* gate  = (const float*)d_in[12];
    float* out = (float*)d_out;

    float* q    = sym<float>(g_q);     float* k    = sym<float>(g_k);
    float* vT   = sym<float>(g_vT);    float* sc   = sym<float>(g_sc);
    float* o    = sym<float>(g_out);   float* proj = sym<float>(g_proj);

    int8_t* rgb1 = sym<int8_t>(g_rgb1);   int8_t* rgb2 = sym<int8_t>(g_rgb2);
    int8_t* pos1 = sym<int8_t>(g_pose1);  int8_t* pos2 = sym<int8_t>(g_pose2);
    float*  srgb = sym<float>(g_srgb);    float*  spos = sym<float>(g_spose);
    int8_t* wq1 = sym<int8_t>(g_wq1); int8_t* wq2 = sym<int8_t>(g_wq2);
    int8_t* wk1 = sym<int8_t>(g_wk1); int8_t* wk2 = sym<int8_t>(g_wk2);
    int8_t* wv1 = sym<int8_t>(g_wv1); int8_t* wv2 = sym<int8_t>(g_wv2);
    int8_t* wp1 = sym<int8_t>(g_wp1); int8_t* wp2 = sym<int8_t>(g_wp2);
    float* swq = sym<float>(g_swq); float* swk = sym<float>(g_swk);
    float* swv = sym<float>(g_swv); float* swp = sym<float>(g_swp);
    int8_t* q1 = sym<int8_t>(g_q1); int8_t* q2 = sym<int8_t>(g_q2);
    int8_t* k1 = sym<int8_t>(g_k1); int8_t* k2 = sym<int8_t>(g_k2);
    float* sq = sym<float>(g_sq);   float* sk = sym<float>(g_sk);
    int8_t* v1 = sym<int8_t>(g_v1); int8_t* v2 = sym<int8_t>(g_v2);
    float* sv = sym<float>(g_sv);
    int8_t* a1 = sym<int8_t>(g_a1); int8_t* a2 = sym<int8_t>(g_a2);
    float* sat = sym<float>(g_sat);
    int8_t* o1 = sym<int8_t>(g_o1); int8_t* o2 = sym<int8_t>(g_o2);
    float* so = sym<float>(g_so);

    const float inv_sqrt_h = 0.044194173824159216f;

    // 0: weight prep (transpose + quantize, all four)
    prep_weights<<<242, 256>>>(Wq, Wk, Wv, Wp);
    // 1,2: activation quantize
    quant_rows<<<MS / 8, 256>>>(rgb,  MS, D_, KP_D, rgb1, rgb2, srgb);
    quant_rows<<<MS / 8, 256>>>(pose, MS, D_, KP_D, pos1, pos2, spos);

    // 3: q = rgb @ Wq + bq
    gemm_i8<<<dim3(H_ / 128, MS / 128, 1), 256>>>(
        rgb1, rgb2, srgb, 0, 0, wq1, wq2, swq, 0, 0,
        q, 0, MS, H_, KP_D, 1.f, bq, nullptr);
    // 4: k = pose @ Wk + bk
    gemm_i8<<<dim3(H_ / 128, MS / 128, 1), 256>>>(
        pos1, pos2, spos, 0, 0, wk1, wk2, swk, 0, 0,
        k, 0, MS, H_, KP_D, 1.f, bk, nullptr);
    // 5: vT[b][h][s] = (pose_b @ Wv + bv)^T   <-- profiled launch
    gemm_i8<<<dim3(S_ / 128, H_ / 128, B_), 256>>>(
        wv1, wv2, swv, 0, 0, pos1, pos2, spos, (long)S_ * KP_D, S_,
        vT, (long)H_ * S_, H_, S_, KP_D, 1.f, nullptr, bv);

    // 6,7,8: quantize q, k, vT
    quant_rows<<<MS / 8, 256>>>(q,  MS, H_, H_, q1, q2, sq);
    quant_rows<<<MS / 8, 256>>>(k,  MS, H_, H_, k1, k2, sk);
    quant_rows<<<(B_ * H_) / 8, 256>>>(vT, B_ * H_, S_, S_, v1, v2, sv);

    // 9: scores = q k^T / sqrt(H)
    gemm_i8<<<dim3(S_ / 128, S_ / 128, B_), 256>>>(
        q1, q2, sq, (long)S_ * H_, S_, k1, k2, sk, (long)S_ * H_, S_,
        sc, (long)S_ * S_, S_, S_, H_, inv_sqrt_h, nullptr, nullptr);

    // 10: softmax -> int8 attn slices
    softmax_q<<<B_ * S_, 256>>>(sc, a1, a2, sat);

    // 11: out = attn @ v
    gemm_i8<<<dim3(H_ / 128, S_ / 128, B_), 256>>>(
        a1, a2, sat, (long)S_ * S_, S_, v1, v2, sv, (long)H_ * S_, H_,
        o, (long)S_ * H_, S_, H_, S_, 1.f, nullptr, nullptr);

    // 12: quantize out
    quant_rows<<<MS / 8, 256>>>(o, MS, H_, H_, o1, o2, so);

    // 13: proj = out @ Wp + bp (N=400 tail)
    gemm_i8<<<dim3((D_ + 127) / 128, MS / 128, 1), 256>>>(
        o1, o2, so, 0, 0, wp1, wp2, swp, 0, 0,
        proj, 0, MS, D_, H_, 1.f, bp, nullptr);

    // 14: LN epilogue
    ln_epilogue<<<B_ * S_, 128>>>(proj, rgb, gate, gamma, beta, out);
}

// round 7
// speedup vs baseline: 1.5665x; 1.5665x over previous
#include <cuda_runtime.h>
#include <math.h>
#include <stdint.h>

#define B_   32
#define S_   2048
#define D_   400
#define H_   512
#define MS   (B_*S_)

__device__ float g_q   [(long)MS*H_];
__device__ float g_k   [(long)MS*H_];
__device__ float g_vT  [(long)B_*H_*S_];
__device__ float g_att [(long)B_*S_*S_];
__device__ float g_out [(long)MS*H_];
__device__ float g_proj[(long)MS*D_];
__device__ float g_WqT [H_*D_];
__device__ float g_WkT [H_*D_];
__device__ float g_WvT [H_*D_];
__device__ float g_WpT [D_*H_];

// ---------------------------------------------------------------------------
__device__ __forceinline__ unsigned f2tf32(float x) {
    unsigned u;
    asm("cvt.rna.tf32.f32 %0, %1;" : "=r"(u) : "f"(x));
    return u;
}

__global__ void transpose_k(const float* __restrict__ in, float* __restrict__ out,
                            int R, int C) {
    int idx = blockIdx.x * blockDim.x + threadIdx.x;
    if (idx < R * C) {
        int r = idx / C, c = idx % C;
        out[c * R + r] = in[idx];
    }
}

#define LDW 20                 // smem row pitch in floats (16 + 4 pad)

// ---------------------------------------------------------------------------
// Hybrid NT GEMM: tensor pipe (tf32 mma, cols 0..103) + fma pipe (fp32 SIMT,
// cols 104..127) running concurrently. ALL warps issue cp.async loads.
// C[m][n] = alpha*sum_k A[m][k]*B[n][k] (+bias_n)(+bias_m)
// Block tile 64x128, K_TILE=16, 256 thr (8 warps: 4 mma + 4 ffma),
// double buffer. Requires M%64==0, K%16==0. N tail guarded.
// ---------------------------------------------------------------------------
__global__ void __launch_bounds__(256, 2)
gemm_hy(const float* __restrict__ A, long sA,
        const float* __restrict__ B, long sB,
        float* __restrict__ C, long sC,
        int M, int N, int K, float alpha,
        const float* __restrict__ bias_n,
        const float* __restrict__ bias_m) {
    __shared__ float As[2][64 * LDW];
    __shared__ float Bs[2][128 * LDW];

    const int tid  = threadIdx.x;
    const int lane = tid & 31;
    const int wid  = tid >> 5;

    const long bz = blockIdx.z;
    A += bz * sA; B += bz * sB; C += bz * sC;
    const int m0 = blockIdx.y * 64;
    const int n0 = blockIdx.x * 128;

    // ---- cp.async mapping: 768 16B chunks (A 256 + B 512), 3 per thread ----
    const float* gsrc[3]; unsigned sdst[2][3], ssz[3];
    {
        unsigned ab[2] = { (unsigned)__cvta_generic_to_shared(As[0]),
                           (unsigned)__cvta_generic_to_shared(As[1]) };
        unsigned bb[2] = { (unsigned)__cvta_generic_to_shared(Bs[0]),
                           (unsigned)__cvta_generic_to_shared(Bs[1]) };
#pragma unroll
        for (int i = 0; i < 3; i++) {
            int c = tid + i * 256;
            if (c < 256) {
                int row = c >> 2, q = c & 3;
                sdst[0][i] = ab[0] + (row * LDW + q * 4) * 4;
                sdst[1][i] = ab[1] + (row * LDW + q * 4) * 4;
                gsrc[i] = A + (long)(m0 + row) * K + q * 4;
                ssz[i] = 16u;
            } else {
                int cc = c - 256;
                int row = cc >> 2, q = cc & 3;
                sdst[0][i] = bb[0] + (row * LDW + q * 4) * 4;
                sdst[1][i] = bb[1] + (row * LDW + q * 4) * 4;
                int gn = n0 + row;
                int ok = gn < N;
                gsrc[i] = B + (long)(ok ? gn : 0) * K + q * 4;
                ssz[i] = ok ? 16u : 0u;
            }
        }
    }

#define LOADST(bf, kb) do {                                                   \
    _Pragma("unroll")                                                         \
    for (int i = 0; i < 3; i++)                                               \
        asm volatile("cp.async.cg.shared.global [%0], [%1], 16, %2;\n"        \
                     :: "r"(sdst[bf][i]), "l"(gsrc[i] + (kb)), "r"(ssz[i]));  \
    asm volatile("cp.async.commit_group;\n");                                 \
} while (0)

    const int T = K / 16;

    // ---- per-role registers ----
    const int wr = wid & 1, wc = wid >> 1;          // mma mapping
    const int jn   = (wc == 1) ? 6 : 7;
    const int joff = (wc == 1) ? 56 : 0;
    const int g = lane >> 2, tg = lane & 3;

    const int fw = wid - 4;                          // ffma mapping
    const int tr = lane & 7, tc = lane >> 3;
    const int rb = ((fw < 0 ? 0 : fw) * 16 + tr * 2);
    const int cb = 104 + tc * 6;

    float acc[2][7][4];                              // mma accum (or reuse below)
    float fac[2][6];                                 // ffma accum
#pragma unroll
    for (int i = 0; i < 2; i++)
#pragma unroll
        for (int j = 0; j < 7; j++)
#pragma unroll
            for (int c = 0; c < 4; c++) acc[i][j][c] = 0.f;
#pragma unroll
    for (int r = 0; r < 2; r++)
#pragma unroll
        for (int c = 0; c < 6; c++) fac[r][c] = 0.f;

    LOADST(0, 0);

    for (int t = 0; t < T; t++) {
        const int buf = t & 1;
        if (t + 1 < T) {
            LOADST(buf ^ 1, (long)(t + 1) * 16);
            asm volatile("cp.async.wait_group 1;\n");
        } else {
            asm volatile("cp.async.wait_group 0;\n");
        }
        __syncthreads();

        if (wid < 4) {
            // ---------------- mma warps: 32 rows x (56|48) cols --------------
#pragma unroll
            for (int kk = 0; kk < 16; kk += 8) {
                unsigned af[2][4], bf[7][2];
#pragma unroll
                for (int i = 0; i < 2; i++) {
                    const float* p = &As[buf][(wr * 32 + i * 16 + g) * LDW + kk + tg];
                    af[i][0] = f2tf32(p[0]);
                    af[i][1] = f2tf32(p[8 * LDW]);
                    af[i][2] = f2tf32(p[4]);
                    af[i][3] = f2tf32(p[8 * LDW + 4]);
                }
#pragma unroll
                for (int j = 0; j < 7; j++) {
                    if (j < jn) {
                        const float* p = &Bs[buf][(joff + j * 8 + g) * LDW + kk + tg];
                        bf[j][0] = f2tf32(p[0]);
                        bf[j][1] = f2tf32(p[4]);
                    }
                }
#pragma unroll
                for (int i = 0; i < 2; i++)
#pragma unroll
                    for (int j = 0; j < 7; j++) {
                        if (j < jn) {
                            asm volatile(
                                "mma.sync.aligned.m16n8k8.row.col.f32.tf32.tf32.f32 "
                                "{%0,%1,%2,%3}, {%4,%5,%6,%7}, {%8,%9}, {%0,%1,%2,%3};\n"
                                : "+f"(acc[i][j][0]), "+f"(acc[i][j][1]),
                                  "+f"(acc[i][j][2]), "+f"(acc[i][j][3])
                                : "r"(af[i][0]), "r"(af[i][1]), "r"(af[i][2]), "r"(af[i][3]),
                                  "r"(bf[j][0]), "r"(bf[j][1]));
                        }
                    }
            }
        } else {
            // ---------------- ffma warps: 64 rows x 24 cols ------------------
#pragma unroll
            for (int q = 0; q < 4; q++) {
                float4 a0 = *(const float4*)&As[buf][(rb + 0) * LDW + q * 4];
                float4 a1 = *(const float4*)&As[buf][(rb + 1) * LDW + q * 4];
                float4 b[6];
#pragma unroll
                for (int c = 0; c < 6; c++)
                    b[c] = *(const float4*)&Bs[buf][(cb + c) * LDW + q * 4];
#pragma unroll
                for (int c = 0; c < 6; c++) {
                    fac[0][c] += a0.x * b[c].x + a0.y * b[c].y
                               + a0.z * b[c].z + a0.w * b[c].w;
                    fac[1][c] += a1.x * b[c].x + a1.y * b[c].y
                               + a1.z * b[c].z + a1.w * b[c].w;
                }
            }
        }
        __syncthreads();
    }

    // ---- epilogues ----
    if (wid < 4) {
#pragma unroll
        for (int i = 0; i < 2; i++) {
            const int r0 = m0 + wr * 32 + i * 16 + g;
            const int r1 = r0 + 8;
            const float bm0 = bias_m ? bias_m[r0] : 0.f;
            const float bm1 = bias_m ? bias_m[r1] : 0.f;
#pragma unroll
            for (int j = 0; j < 7; j++) {
                if (j < jn) {
                    const int c0 = n0 + joff + j * 8 + 2 * tg;
                    if (c0 < N) {
                        const float bn0 = bias_n ? bias_n[c0]     : 0.f;
                        const float bn1 = bias_n ? bias_n[c0 + 1] : 0.f;
                        *(float2*)&C[(long)r0 * N + c0] =
                            make_float2(acc[i][j][0] * alpha + bm0 + bn0,
                                        acc[i][j][1] * alpha + bm0 + bn1);
                        *(float2*)&C[(long)r1 * N + c0] =
                            make_float2(acc[i][j][2] * alpha + bm1 + bn0,
                                        acc[i][j][3] * alpha + bm1 + bn1);
                    }
                }
            }
        }
    } else {
#pragma unroll
        for (int r = 0; r < 2; r++) {
            const int gr = m0 + rb + r;
            const float bm = bias_m ? bias_m[gr] : 0.f;
#pragma unroll
            for (int c = 0; c < 6; c++) {
                const int gc = n0 + cb + c;
                if (gc < N) {
                    float v = fac[r][c] * alpha + bm;
                    if (bias_n) v += bias_n[gc];
                    C[(long)gr * N + gc] = v;
                }
            }
        }
    }
#undef LOADST
}

// ---------------------------------------------------------------------------
__global__ void __launch_bounds__(256)
softmax2048(float* __restrict__ data) {
    float* row = data + (long)blockIdx.x * 2048;
    const int tid = threadIdx.x;
    __shared__ float red[8];

    float v[8];
    float m = -3.4e38f;
#pragma unroll
    for (int i = 0; i < 8; i++) { v[i] = row[tid + i * 256]; m = fmaxf(m, v[i]); }
#pragma unroll
    for (int o = 16; o > 0; o >>= 1) m = fmaxf(m, __shfl_xor_sync(~0u, m, o));
    if ((tid & 31) == 0) red[tid >> 5] = m;
    __syncthreads();
    float rowmax = red[0];
#pragma unroll
    for (int w = 1; w < 8; w++) rowmax = fmaxf(rowmax, red[w]);
    __syncthreads();

    float s = 0.f;
#pragma unroll
    for (int i = 0; i < 8; i++) { v[i] = __expf(v[i] - rowmax); s += v[i]; }
#pragma unroll
    for (int o = 16; o > 0; o >>= 1) s += __shfl_xor_sync(~0u, s, o);
    if ((tid & 31) == 0) red[tid >> 5] = s;
    __syncthreads();
    float tot = 0.f;
#pragma unroll
    for (int w = 0; w < 8; w++) tot += red[w];
    float inv = 1.f / tot;
#pragma unroll
    for (int i = 0; i < 8; i++) row[tid + i * 256] = v[i] * inv;
}

// ---------------------------------------------------------------------------
__global__ void __launch_bounds__(128)
ln_epilogue(const float* __restrict__ proj, const float* __restrict__ rgb,
            const float* __restrict__ gate, const float* __restrict__ gamma,
            const float* __restrict__ beta, float* __restrict__ out) {
    const long row = blockIdx.x;
    const int tid = threadIdx.x;
    const float g = gate[0];
    __shared__ float xs[D_];
    __shared__ float red[4];

    float s = 0.f;
    for (int i = tid; i < D_; i += 128) {
        float x = rgb[row * D_ + i] + g * proj[row * D_ + i];
        xs[i] = x;
        s += x;
    }
#pragma unroll
    for (int o = 16; o > 0; o >>= 1) s += __shfl_xor_sync(~0u, s, o);
    if ((tid & 31) == 0) red[tid >> 5] = s;
    __syncthreads();
    float mu = (red[0] + red[1] + red[2] + red[3]) * (1.0f / D_);
    __syncthreads();

    float vs = 0.f;
    for (int i = tid; i < D_; i += 128) {
        float d = xs[i] - mu;
        vs += d * d;
    }
#pragma unroll
    for (int o = 16; o > 0; o >>= 1) vs += __shfl_xor_sync(~0u, vs, o);
    if ((tid & 31) == 0) red[tid >> 5] = vs;
    __syncthreads();
    float var = (red[0] + red[1] + red[2] + red[3]) * (1.0f / D_);
    float inv = rsqrtf(var + 1e-5f);

    for (int i = tid; i < D_; i += 128) {
        out[row * D_ + i] = (xs[i] - mu) * inv * gamma[i] + beta[i];
    }
}

// ---------------------------------------------------------------------------
static float* sym(const void* s) {
    void* p = nullptr;
    cudaGetSymbolAddress(&p, s);
    return (float*)p;
}

extern "C" void kernel_launch(void* const* d_in, const int* in_sizes, int n_in,
                              void* d_out, int out_size) {
    const float* rgb   = (const float*)d_in[0];
    const float* pose  = (const float*)d_in[1];
    const float* Wq    = (const float*)d_in[2];
    const float* bq    = (const float*)d_in[3];
    const float* Wk    = (const float*)d_in[4];
    const float* bk    = (const float*)d_in[5];
    const float* Wv    = (const float*)d_in[6];
    const float* bv    = (const float*)d_in[7];
    const float* Wp    = (const float*)d_in[8];
    const float* bp    = (const float*)d_in[9];
    const float* gamma = (const float*)d_in[10];
    const float* beta  = (const float*)d_in[11];
    const float* gate  = (const float*)d_in[12];
    float* out = (float*)d_out;

    float* q    = sym(g_q);    float* k    = sym(g_k);
    float* vT   = sym(g_vT);   float* att  = sym(g_att);
    float* o    = sym(g_out);  float* proj = sym(g_proj);
    float* WqT  = sym(g_WqT);  float* WkT  = sym(g_WkT);
    float* WvT  = sym(g_WvT);  float* WpT  = sym(g_WpT);

    const float inv_sqrt_h = 0.044194173824159216f;

    {
        int n1 = D_ * H_;
        transpose_k<<<(n1 + 255) / 256, 256>>>(Wq, WqT, D_, H_);
        transpose_k<<<(n1 + 255) / 256, 256>>>(Wk, WkT, D_, H_);
        transpose_k<<<(n1 + 255) / 256, 256>>>(Wv, WvT, D_, H_);
        transpose_k<<<(n1 + 255) / 256, 256>>>(Wp, WpT, H_, D_);
    }

    // q = rgb @ Wq + bq
    gemm_hy<<<dim3(H_ / 128, MS / 64, 1), 256>>>(
        rgb, 0, WqT, 0, q, 0, MS, H_, D_, 1.f, bq, nullptr);
    // k = pose @ Wk + bk
    gemm_hy<<<dim3(H_ / 128, MS / 64, 1), 256>>>(
        pose, 0, WkT, 0, k, 0, MS, H_, D_, 1.f, bk, nullptr);
    // vT[b][h][s] = (pose_b @ Wv + bv)^T
    gemm_hy<<<dim3(S_ / 128, H_ / 64, B_), 256>>>(
        WvT, 0, pose, (long)S_ * D_, vT, (long)H_ * S_,
        H_, S_, D_, 1.f, nullptr, bv);

    // scores = q k^T / sqrt(H)
    gemm_hy<<<dim3(S_ / 128, S_ / 64, B_), 256>>>(
        q, (long)S_ * H_, k, (long)S_ * H_, att, (long)S_ * S_,
        S_, S_, H_, inv_sqrt_h, nullptr, nullptr);

    softmax2048<<<B_ * S_, 256>>>(att);

    // out = attn @ v
    gemm_hy<<<dim3(H_ / 128, S_ / 64, B_), 256>>>(
        att, (long)S_ * S_, vT, (long)H_ * S_, o, (long)S_ * H_,
        S_, H_, S_, 1.f, nullptr, nullptr);

    // proj = out @ Wp + bp  (N=400 tail)
    gemm_hy<<<dim3((D_ + 127) / 128, MS / 64, 1), 256>>>(
        o, 0, WpT, 0, proj, 0, MS, D_, H_, 1.f, bp, nullptr);

    ln_epilogue<<<B_ * S_, 128>>>(proj, rgb, gate, gamma, beta, out);
}

// round 8
// speedup vs baseline: 3.4086x; 2.1760x over previous
#include <cuda_runtime.h>
#include <math.h>
#include <stdint.h>

#define B_   32
#define S_   2048
#define D_   400
#define H_   512
#define MS   (B_*S_)

__device__ float g_q   [(long)MS*H_];
__device__ float g_k   [(long)MS*H_];
__device__ float g_vT  [(long)B_*H_*S_];
__device__ float g_att [(long)B_*S_*S_];
__device__ float g_out [(long)MS*H_];
__device__ float g_proj[(long)MS*D_];
__device__ float g_part[(long)MS*16];     // per-(row, col-block) exp partial sums
__device__ float g_WqT [H_*D_];
__device__ float g_WkT [H_*D_];
__device__ float g_WvT [H_*D_];
__device__ float g_WpT [D_*H_];

// ---------------------------------------------------------------------------
__device__ __forceinline__ unsigned f2tf32(float x) {
    unsigned u;
    asm("cvt.rna.tf32.f32 %0, %1;" : "=r"(u) : "f"(x));
    return u;
}

__global__ void transpose_k(const float* __restrict__ in, float* __restrict__ out,
                            int R, int C) {
    int idx = blockIdx.x * blockDim.x + threadIdx.x;
    if (idx < R * C) {
        int r = idx / C, c = idx % C;
        out[c * R + r] = in[idx];
    }
}

#define SMEM_LD 20   // 16 k-floats + 4 pad => conflict-free fragment loads

// ---------------------------------------------------------------------------
// NT GEMM on tensor cores (tf32 mma.sync m16n8k8).
// C[m][n] = alpha * sum_k A[m][k]*B[n][k] (+bias_n[n]) (+bias_m[m])
// Block 128x128x16, 256 thr (8 warps, 2x4 grid of 64x32 warp tiles),
// cp.async double buffer. M%128==0, K%16==0; N tail guarded.
// Fused-softmax hooks:
//   part_out != 0: C gets exp(alpha*acc); per-row partial sums of exp over this
//                  block's 128 cols go to part_out[(z*M+row)*16 + blockIdx.x].
//   part_in  != 0: epilogue multiplies by alpha / rowsum (rowsum = sum of the
//                  16 partials for that row). alpha ignored otherwise in factor.
// ---------------------------------------------------------------------------
__global__ void __launch_bounds__(256, 2)
gemm_tf32(const float* __restrict__ A, long sA,
          const float* __restrict__ B, long sB,
          float* __restrict__ C, long sC,
          int M, int N, int K, float alpha,
          const float* __restrict__ bias_n,
          const float* __restrict__ bias_m,
          float* __restrict__ part_out,
          const float* __restrict__ part_in) {
    __shared__ float As[2][128 * SMEM_LD];
    __shared__ float Bs[2][128 * SMEM_LD];
    __shared__ float rcp[128];

    const int tid  = threadIdx.x;
    const int lane = tid & 31;
    const int wid  = tid >> 5;
    const int wr   = wid & 1;        // warp row (0..1) -> 64 rows each
    const int wc   = wid >> 1;       // warp col (0..3) -> 32 cols each
    const int g    = lane >> 2;      // groupID
    const int tg   = lane & 3;       // threadID_in_group

    const long bz = blockIdx.z;
    A += bz * sA; B += bz * sB; C += bz * sC;
    const int m0 = blockIdx.y * 128;
    const int n0 = blockIdx.x * 128;

    // ---- div-mode prologue: rcp[row] = alpha / sum(16 partials) ----
    if (part_in) {
        float* sc2 = &As[0][0];                       // 256-float scratch
        {
            int row = tid >> 1, half = tid & 1;
            const float* pp = part_in + ((long)bz * M + m0 + row) * 16 + half * 8;
            float s = ((pp[0] + pp[1]) + (pp[2] + pp[3]))
                    + ((pp[4] + pp[5]) + (pp[6] + pp[7]));
            sc2[row * 2 + half] = s;
        }
        __syncthreads();
        if (tid < 128) rcp[tid] = alpha / (sc2[2 * tid] + sc2[2 * tid + 1]);
        __syncthreads();
    }

    // copy mapping: 256 thr, each does 2 rows (r, r+64), one float4 of k
    const int ldr = tid >> 2;            // 0..63
    const int ldc = (tid & 3) * 4;       // 0,4,8,12

    const float* Ag0 = A + (long)(m0 + ldr) * K + ldc;
    const float* Ag1 = Ag0 + (long)64 * K;
    const int bn0 = n0 + ldr;
    const bool v0 = bn0 < N, v1 = (bn0 + 64) < N;
    const float* Bg0 = B + (long)(v0 ? bn0 : 0) * K + ldc;
    const float* Bg1 = B + (long)(v1 ? bn0 + 64 : 0) * K + ldc;
    const unsigned z0 = v0 ? 16u : 0u, z1 = v1 ? 16u : 0u;

    unsigned sa[2], sb[2];
    sa[0] = (unsigned)__cvta_generic_to_shared(&As[0][ldr * SMEM_LD + ldc]);
    sa[1] = (unsigned)__cvta_generic_to_shared(&As[1][ldr * SMEM_LD + ldc]);
    sb[0] = (unsigned)__cvta_generic_to_shared(&Bs[0][ldr * SMEM_LD + ldc]);
    sb[1] = (unsigned)__cvta_generic_to_shared(&Bs[1][ldr * SMEM_LD + ldc]);
    const unsigned off64 = 64 * SMEM_LD * 4;

    float acc[4][4][4];
#pragma unroll
    for (int i = 0; i < 4; i++)
#pragma unroll
        for (int j = 0; j < 4; j++)
#pragma unroll
            for (int c = 0; c < 4; c++) acc[i][j][c] = 0.f;

    const int T = K / 16;

    asm volatile("cp.async.cg.shared.global [%0], [%1], 16;\n" :: "r"(sa[0]), "l"(Ag0));
    asm volatile("cp.async.cg.shared.global [%0], [%1], 16;\n" :: "r"(sa[0] + off64), "l"(Ag1));
    asm volatile("cp.async.cg.shared.global [%0], [%1], 16, %2;\n" :: "r"(sb[0]), "l"(Bg0), "r"(z0));
    asm volatile("cp.async.cg.shared.global [%0], [%1], 16, %2;\n" :: "r"(sb[0] + off64), "l"(Bg1), "r"(z1));
    asm volatile("cp.async.commit_group;\n");

    for (int t = 0; t < T; t++) {
        const int buf = t & 1;
        if (t + 1 < T) {
            const int nb = buf ^ 1;
            const long k0 = (long)(t + 1) * 16;
            asm volatile("cp.async.cg.shared.global [%0], [%1], 16;\n" :: "r"(sa[nb]), "l"(Ag0 + k0));
            asm volatile("cp.async.cg.shared.global [%0], [%1], 16;\n" :: "r"(sa[nb] + off64), "l"(Ag1 + k0));
            asm volatile("cp.async.cg.shared.global [%0], [%1], 16, %2;\n" :: "r"(sb[nb]), "l"(Bg0 + k0), "r"(z0));
            asm volatile("cp.async.cg.shared.global [%0], [%1], 16, %2;\n" :: "r"(sb[nb] + off64), "l"(Bg1 + k0), "r"(z1));
            asm volatile("cp.async.commit_group;\n");
            asm volatile("cp.async.wait_group 1;\n");
        } else {
            asm volatile("cp.async.wait_group 0;\n");
        }
        __syncthreads();

#pragma unroll
        for (int kk = 0; kk < 16; kk += 8) {
            unsigned af[4][4], bf[4][2];
#pragma unroll
            for (int i = 0; i < 4; i++) {
                const float* p = &As[buf][(wr * 64 + i * 16 + g) * SMEM_LD + kk + tg];
                af[i][0] = f2tf32(p[0]);
                af[i][1] = f2tf32(p[8 * SMEM_LD]);
                af[i][2] = f2tf32(p[4]);
                af[i][3] = f2tf32(p[8 * SMEM_LD + 4]);
            }
#pragma unroll
            for (int j = 0; j < 4; j++) {
                const float* p = &Bs[buf][(wc * 32 + j * 8 + g) * SMEM_LD + kk + tg];
                bf[j][0] = f2tf32(p[0]);
                bf[j][1] = f2tf32(p[4]);
            }
#pragma unroll
            for (int i = 0; i < 4; i++)
#pragma unroll
                for (int j = 0; j < 4; j++) {
                    asm volatile(
                        "mma.sync.aligned.m16n8k8.row.col.f32.tf32.tf32.f32 "
                        "{%0,%1,%2,%3}, {%4,%5,%6,%7}, {%8,%9}, {%0,%1,%2,%3};\n"
                        : "+f"(acc[i][j][0]), "+f"(acc[i][j][1]),
                          "+f"(acc[i][j][2]), "+f"(acc[i][j][3])
                        : "r"(af[i][0]), "r"(af[i][1]), "r"(af[i][2]), "r"(af[i][3]),
                          "r"(bf[j][0]), "r"(bf[j][1]));
                }
        }
        __syncthreads();
    }

    // ---- epilogue ----
    float* sred = &As[0][0];   // 512-float scratch for exp partials (mainloop done)

#pragma unroll
    for (int i = 0; i < 4; i++) {
        const int r0loc = wr * 64 + i * 16 + g;
        const int r1loc = r0loc + 8;
        const int r0 = m0 + r0loc, r1 = m0 + r1loc;
        float f0 = alpha, f1 = alpha;
        if (part_in) { f0 = rcp[r0loc]; f1 = rcp[r1loc]; }
        const float bm0 = bias_m ? bias_m[r0] : 0.f;
        const float bm1 = bias_m ? bias_m[r1] : 0.f;
        float s0 = 0.f, s1 = 0.f;
#pragma unroll
        for (int j = 0; j < 4; j++) {
            const int c0 = n0 + wc * 32 + j * 8 + 2 * tg;
            if (c0 < N) {
                const float bn0 = bias_n ? bias_n[c0]     : 0.f;
                const float bn1 = bias_n ? bias_n[c0 + 1] : 0.f;
                float v00 = acc[i][j][0] * f0 + bm0 + bn0;
                float v01 = acc[i][j][1] * f0 + bm0 + bn1;
                float v10 = acc[i][j][2] * f1 + bm1 + bn0;
                float v11 = acc[i][j][3] * f1 + bm1 + bn1;
                if (part_out) {
                    v00 = __expf(v00); v01 = __expf(v01);
                    v10 = __expf(v10); v11 = __expf(v11);
                    s0 += v00 + v01;  s1 += v10 + v11;
                }
                *(float2*)&C[(long)r0 * N + c0] = make_float2(v00, v01);
                *(float2*)&C[(long)r1 * N + c0] = make_float2(v10, v11);
            }
        }
        if (part_out) {
            // reduce across the 4 lanes of the quad (same g, tg = 0..3)
            s0 += __shfl_xor_sync(~0u, s0, 1);  s0 += __shfl_xor_sync(~0u, s0, 2);
            s1 += __shfl_xor_sync(~0u, s1, 1);  s1 += __shfl_xor_sync(~0u, s1, 2);
            if (tg == 0) {
                sred[wc * 128 + r0loc] = s0;
                sred[wc * 128 + r1loc] = s1;
            }
        }
    }

    if (part_out) {
        __syncthreads();
        if (tid < 128) {
            float p = (sred[tid] + sred[128 + tid])
                    + (sred[256 + tid] + sred[384 + tid]);
            part_out[((long)bz * M + m0 + tid) * 16 + blockIdx.x] = p;
        }
    }
}

// ---------------------------------------------------------------------------
__global__ void __launch_bounds__(128)
ln_epilogue(const float* __restrict__ proj, const float* __restrict__ rgb,
            const float* __restrict__ gate, const float* __restrict__ gamma,
            const float* __restrict__ beta, float* __restrict__ out) {
    const long row = blockIdx.x;
    const int tid = threadIdx.x;
    const float g = gate[0];
    __shared__ float xs[D_];
    __shared__ float red[4];

    float s = 0.f;
    for (int i = tid; i < D_; i += 128) {
        float x = rgb[row * D_ + i] + g * proj[row * D_ + i];
        xs[i] = x;
        s += x;
    }
#pragma unroll
    for (int o = 16; o > 0; o >>= 1) s += __shfl_xor_sync(~0u, s, o);
    if ((tid & 31) == 0) red[tid >> 5] = s;
    __syncthreads();
    float mu = (red[0] + red[1] + red[2] + red[3]) * (1.0f / D_);
    __syncthreads();

    float vs = 0.f;
    for (int i = tid; i < D_; i += 128) {
        float d = xs[i] - mu;
        vs += d * d;
    }
#pragma unroll
    for (int o = 16; o > 0; o >>= 1) vs += __shfl_xor_sync(~0u, vs, o);
    if ((tid & 31) == 0) red[tid >> 5] = vs;
    __syncthreads();
    float var = (red[0] + red[1] + red[2] + red[3]) * (1.0f / D_);
    float inv = rsqrtf(var + 1e-5f);

    for (int i = tid; i < D_; i += 128) {
        out[row * D_ + i] = (xs[i] - mu) * inv * gamma[i] + beta[i];
    }
}

// ---------------------------------------------------------------------------
static float* sym(const void* s) {
    void* p = nullptr;
    cudaGetSymbolAddress(&p, s);
    return (float*)p;
}

extern "C" void kernel_launch(void* const* d_in, const int* in_sizes, int n_in,
                              void* d_out, int out_size) {
    const float* rgb   = (const float*)d_in[0];
    const float* pose  = (const float*)d_in[1];
    const float* Wq    = (const float*)d_in[2];
    const float* bq    = (const float*)d_in[3];
    const float* Wk    = (const float*)d_in[4];
    const float* bk    = (const float*)d_in[5];
    const float* Wv    = (const float*)d_in[6];
    const float* bv    = (const float*)d_in[7];
    const float* Wp    = (const float*)d_in[8];
    const float* bp    = (const float*)d_in[9];
    const float* gamma = (const float*)d_in[10];
    const float* beta  = (const float*)d_in[11];
    const float* gate  = (const float*)d_in[12];
    float* out = (float*)d_out;

    float* q    = sym(g_q);    float* k    = sym(g_k);
    float* vT   = sym(g_vT);   float* att  = sym(g_att);
    float* o    = sym(g_out);  float* proj = sym(g_proj);
    float* part = sym(g_part);
    float* WqT  = sym(g_WqT);  float* WkT  = sym(g_WkT);
    float* WvT  = sym(g_WvT);  float* WpT  = sym(g_WpT);

    const float inv_sqrt_h = 0.044194173824159216f;  // 1/sqrt(512)

    {
        int n1 = D_ * H_;
        transpose_k<<<(n1 + 255) / 256, 256>>>(Wq, WqT, D_, H_);
        transpose_k<<<(n1 + 255) / 256, 256>>>(Wk, WkT, D_, H_);
        transpose_k<<<(n1 + 255) / 256, 256>>>(Wv, WvT, D_, H_);
        transpose_k<<<(n1 + 255) / 256, 256>>>(Wp, WpT, H_, D_);
    }

    // q = rgb @ Wq + bq
    gemm_tf32<<<dim3(H_ / 128, MS / 128, 1), 256>>>(
        rgb, 0, WqT, 0, q, 0, MS, H_, D_, 1.f, bq, nullptr, nullptr, nullptr);
    // k = pose @ Wk + bk
    gemm_tf32<<<dim3(H_ / 128, MS / 128, 1), 256>>>(
        pose, 0, WkT, 0, k, 0, MS, H_, D_, 1.f, bk, nullptr, nullptr, nullptr);
    // vT[b][h][s] = (pose_b @ Wv + bv)^T
    gemm_tf32<<<dim3(S_ / 128, H_ / 128, B_), 256>>>(
        WvT, 0, pose, (long)S_ * D_, vT, (long)H_ * S_,
        H_, S_, D_, 1.f, nullptr, bv, nullptr, nullptr);

    // att = exp(q k^T / sqrt(H))  +  per-row partial sums (fused softmax pt 1)
    gemm_tf32<<<dim3(S_ / 128, S_ / 128, B_), 256>>>(
        q, (long)S_ * H_, k, (long)S_ * H_, att, (long)S_ * S_,
        S_, S_, H_, inv_sqrt_h, nullptr, nullptr, part, nullptr);

    // out = (att @ v) / rowsum  (fused softmax pt 2)
    gemm_tf32<<<dim3(H_ / 128, S_ / 128, B_), 256>>>(
        att, (long)S_ * S_, vT, (long)H_ * S_, o, (long)S_ * H_,
        S_, H_, S_, 1.f, nullptr, nullptr, nullptr, part);

    // proj = out @ Wp + bp  (N=400 tail guarded)
    gemm_tf32<<<dim3((D_ + 127) / 128, MS / 128, 1), 256>>>(
        o, 0, WpT, 0, proj, 0, MS, D_, H_, 1.f, bp, nullptr, nullptr, nullptr);

    // fused = LN(rgb + gate*proj)
    ln_epilogue<<<B_ * S_, 128>>>(proj, rgb, gate, gamma, beta, out);
}